// round 2
// baseline (speedup 1.0000x reference)
#include <cuda_runtime.h>
#include <math_constants.h>

#define BB 64
#define CC 256
#define CS 64
#define HW 4096
#define NCL 8

// Scratch (allocation-free rule: __device__ globals)
__device__ float g_pooled[BB*CC];
__device__ float g_xmin[BB*CC];
__device__ float g_xmax[BB*CC];
__device__ float g_scale[BB*CC];
__device__ float g_smin[BB];
__device__ float g_smax[BB];
__device__ float g_ss[BB];
__device__ float g_zz[BB];

// -------- Kernel 1: per-(b,c) sum/min/max over HW (one 268MB read) --------
__global__ void k1_stats(const float* __restrict__ x) {
    int bc = blockIdx.x;                       // 0 .. B*C-1
    const float4* xv = (const float4*)(x + (size_t)bc * HW);
    int t = threadIdx.x;                       // 256 threads, 16 elems each
    float s = 0.f, mn = CUDART_INF_F, mx = -CUDART_INF_F;
#pragma unroll
    for (int i = 0; i < 4; i++) {
        float4 v = xv[t + i*256];
        s += v.x + v.y + v.z + v.w;
        mn = fminf(mn, fminf(fminf(v.x, v.y), fminf(v.z, v.w)));
        mx = fmaxf(mx, fmaxf(fmaxf(v.x, v.y), fmaxf(v.z, v.w)));
    }
#pragma unroll
    for (int o = 16; o > 0; o >>= 1) {
        s  += __shfl_xor_sync(0xFFFFFFFFu, s, o);
        mn  = fminf(mn, __shfl_xor_sync(0xFFFFFFFFu, mn, o));
        mx  = fmaxf(mx, __shfl_xor_sync(0xFFFFFFFFu, mx, o));
    }
    __shared__ float rs[8], rmn[8], rmx[8];
    int w = t >> 5, l = t & 31;
    if (l == 0) { rs[w] = s; rmn[w] = mn; rmx[w] = mx; }
    __syncthreads();
    if (t == 0) {
        float S = rs[0], MN = rmn[0], MX = rmx[0];
#pragma unroll
        for (int i = 1; i < 8; i++) {
            S += rs[i]; MN = fminf(MN, rmn[i]); MX = fmaxf(MX, rmx[i]);
        }
        g_pooled[bc] = S * (1.0f / HW);
        g_xmin[bc] = MN;
        g_xmax[bc] = MX;
    }
}

// -------- Kernel 2: per-batch SE MLP + hardsigmoid + per-sample min/max ----
__global__ void k2_scale(const float* __restrict__ w1, const float* __restrict__ b1,
                         const float* __restrict__ w2, const float* __restrict__ b2) {
    int b = blockIdx.x;       // 0..63
    int t = threadIdx.x;      // 256
    __shared__ float sp[CC], sh[CS];
    sp[t] = g_pooled[b*CC + t];
    __syncthreads();
    if (t < CS) {
        float acc = b1[t];
        const float* wr = w1 + t*CC;
#pragma unroll 8
        for (int c = 0; c < CC; c++) acc = fmaf(sp[c], wr[c], acc);
        sh[t] = fmaxf(acc, 0.0f);   // relu
    }
    __syncthreads();
    float v = b2[t];
    const float* w2r = w2 + t*CS;
#pragma unroll 8
    for (int s = 0; s < CS; s++) v = fmaf(sh[s], w2r[s], v);
    float sc = fminf(fmaxf(v / 6.0f + 0.5f, 0.0f), 1.0f);   // hardsigmoid
    g_scale[b*CC + t] = sc;
    // scale >= 0  =>  min/max over plane factor through per-(b,c) extrema
    float pm = sc * g_xmin[b*CC + t];
    float pM = sc * g_xmax[b*CC + t];
#pragma unroll
    for (int o = 16; o > 0; o >>= 1) {
        pm = fminf(pm, __shfl_xor_sync(0xFFFFFFFFu, pm, o));
        pM = fmaxf(pM, __shfl_xor_sync(0xFFFFFFFFu, pM, o));
    }
    __shared__ float rmn[8], rmx[8];
    int w = t >> 5, l = t & 31;
    if (l == 0) { rmn[w] = pm; rmx[w] = pM; }
    __syncthreads();
    if (t == 0) {
        float MN = rmn[0], MX = rmx[0];
#pragma unroll
        for (int i = 1; i < 8; i++) { MN = fminf(MN, rmn[i]); MX = fmaxf(MX, rmx[i]); }
        g_smin[b] = MN;
        g_smax[b] = MX;
    }
}

// -------- Kernel 3: cluster segment min/max, EMA, quant params, per-sample s/z
__global__ void k3_params(const float* __restrict__ act_range,
                          const int* __restrict__ cl) {
    __shared__ float s_s[NCL], s_z[NCL];
    int t = threadIdx.x;   // 64 threads
    if (t < NCL) {
        float cmin = CUDART_INF_F, cmax = -CUDART_INF_F;
        for (int b = 0; b < BB; b++) {
            if (cl[b] == t) {
                cmin = fminf(cmin, g_smin[b]);
                cmax = fmaxf(cmax, g_smax[b]);
            }
        }
        float nmin = act_range[t*2 + 0] * 0.995f + cmin * 0.005f;
        float nmax = act_range[t*2 + 1] * 0.995f + cmax * 0.005f;
        float s = (nmax - nmin) / 255.0f;
        float z = -rintf(nmin / s);
        s_s[t] = s; s_z[t] = z;
    }
    __syncthreads();
    int c = cl[t];
    g_ss[t] = s_s[c];
    g_zz[t] = s_z[c];
}

// -------- Kernel 4: elementwise fake-quant (268MB read + 268MB write) ------
__global__ void k4_quant(const float* __restrict__ x, float* __restrict__ out) {
    int bc = blockIdx.x;
    int b = bc >> 8;
    float sc  = g_scale[bc];
    float ssv = g_ss[b];
    float zzv = g_zz[b];
    float inv = 1.0f / ssv;   // one exact IEEE division per block (no per-elem MUFU)
    const float4* xv = (const float4*)(x + (size_t)bc * HW);
    float4* ov = (float4*)(out + (size_t)bc * HW);
    int t = threadIdx.x;
#pragma unroll
    for (int i = 0; i < 4; i++) {
        float4 v = xv[t + i*256];
        float4 r;
#define FQ(F) {                                     \
        float o  = sc * v.F;                        \
        float y0 = o * inv;                         \
        float rr = fmaf(-ssv, y0, o);               \
        float y  = fmaf(rr, inv, y0);   /* ~correctly rounded o/ssv */ \
        float q  = rintf(y + zzv);                  \
        q = fminf(fmaxf(q, 0.0f), 255.0f);          \
        r.F = (q - zzv) * ssv; }
        FQ(x) FQ(y) FQ(z) FQ(w)
#undef FQ
        ov[t + i*256] = r;
    }
}

extern "C" void kernel_launch(void* const* d_in, const int* in_sizes, int n_in,
                              void* d_out, int out_size) {
    const float* x         = (const float*)d_in[0];
    const float* w1        = (const float*)d_in[1];
    const float* b1        = (const float*)d_in[2];
    const float* w2        = (const float*)d_in[3];
    const float* b2        = (const float*)d_in[4];
    const float* act_range = (const float*)d_in[5];
    const int*   scl       = (const int*)d_in[6];
    float* out = (float*)d_out;

    k1_stats<<<BB*CC, 256>>>(x);
    k2_scale<<<BB, 256>>>(w1, b1, w2, b2);
    k3_params<<<1, 64>>>(act_range, scl);
    k4_quant<<<BB*CC, 256>>>(x, out);
    (void)in_sizes; (void)n_in; (void)out_size;
}

// round 3
// speedup vs baseline: 1.0118x; 1.0118x over previous
#include <cuda_runtime.h>
#include <math_constants.h>

#define BB 64
#define CC 256
#define CS 64
#define HW 4096
#define NCL 8

// Scratch (allocation-free rule: __device__ globals)
__device__ float    g_pooled[BB*CC];
__device__ float    g_xmin[BB*CC];
__device__ float    g_xmax[BB*CC];
__device__ float    g_scale[BB*CC];
__device__ unsigned g_cmin_u[NCL];   // order-preserving-encoded cluster min
__device__ unsigned g_cmax_u[NCL];   // order-preserving-encoded cluster max

// Order-preserving float <-> uint encoding (monotone under unsigned compare)
__device__ __forceinline__ unsigned flipf(float f) {
    unsigned u = __float_as_uint(f);
    return (u & 0x80000000u) ? ~u : (u | 0x80000000u);
}
__device__ __forceinline__ float unflipf(unsigned u) {
    u = (u & 0x80000000u) ? (u & 0x7FFFFFFFu) : ~u;
    return __uint_as_float(u);
}

// -------- Kernel 1: per-(b,c) sum/min/max, warp-per-plane (268MB read) -----
__global__ void k1_stats(const float* __restrict__ x) {
    // reset cluster accumulators for this launch (k2 runs after -> ordered)
    if (blockIdx.x == 0 && threadIdx.x < NCL) {
        g_cmin_u[threadIdx.x] = 0xFFFFFFFFu;   // unsigned-min identity
        g_cmax_u[threadIdx.x] = 0u;            // unsigned-max identity
    }
    int plane = (blockIdx.x * blockDim.x + threadIdx.x) >> 5;  // 0..16383
    int lane  = threadIdx.x & 31;
    const float4* xv = (const float4*)(x + (size_t)plane * HW);
    float s = 0.f, mn = CUDART_INF_F, mx = -CUDART_INF_F;
#pragma unroll 8
    for (int j = 0; j < 32; j++) {
        float4 v = xv[lane + j * 32];
        s += (v.x + v.y) + (v.z + v.w);
        mn = fminf(mn, fminf(fminf(v.x, v.y), fminf(v.z, v.w)));
        mx = fmaxf(mx, fmaxf(fmaxf(v.x, v.y), fmaxf(v.z, v.w)));
    }
#pragma unroll
    for (int o = 16; o > 0; o >>= 1) {
        s  += __shfl_xor_sync(0xFFFFFFFFu, s, o);
        mn  = fminf(mn, __shfl_xor_sync(0xFFFFFFFFu, mn, o));
        mx  = fmaxf(mx, __shfl_xor_sync(0xFFFFFFFFu, mx, o));
    }
    if (lane == 0) {
        g_pooled[plane] = s * (1.0f / HW);
        g_xmin[plane]   = mn;
        g_xmax[plane]   = mx;
    }
}

// -------- Kernel 2: SE MLP + hardsigmoid + per-sample min/max -> cluster ---
__global__ void k2_scale(const float* __restrict__ w1, const float* __restrict__ b1,
                         const float* __restrict__ w2, const float* __restrict__ b2,
                         const int* __restrict__ cl) {
    int b = blockIdx.x;       // 0..63
    int t = threadIdx.x;      // 256
    __shared__ float sp[CC], sh[CS];
    sp[t] = g_pooled[b*CC + t];
    __syncthreads();
    if (t < CS) {
        float acc = b1[t];
        const float* wr = w1 + t*CC;
#pragma unroll 8
        for (int c = 0; c < CC; c++) acc = fmaf(sp[c], wr[c], acc);
        sh[t] = fmaxf(acc, 0.0f);   // relu
    }
    __syncthreads();
    float v = b2[t];
    const float* w2r = w2 + t*CS;
#pragma unroll 8
    for (int s = 0; s < CS; s++) v = fmaf(sh[s], w2r[s], v);
    float sc = fminf(fmaxf(v / 6.0f + 0.5f, 0.0f), 1.0f);   // hardsigmoid
    g_scale[b*CC + t] = sc;
    // scale >= 0  =>  plane extrema factor through per-(b,c) extrema
    float pm = sc * g_xmin[b*CC + t];
    float pM = sc * g_xmax[b*CC + t];
#pragma unroll
    for (int o = 16; o > 0; o >>= 1) {
        pm = fminf(pm, __shfl_xor_sync(0xFFFFFFFFu, pm, o));
        pM = fmaxf(pM, __shfl_xor_sync(0xFFFFFFFFu, pM, o));
    }
    __shared__ float rmn[8], rmx[8];
    int w = t >> 5, l = t & 31;
    if (l == 0) { rmn[w] = pm; rmx[w] = pM; }
    __syncthreads();
    if (t == 0) {
        float MN = rmn[0], MX = rmx[0];
#pragma unroll
        for (int i = 1; i < 8; i++) { MN = fminf(MN, rmn[i]); MX = fmaxf(MX, rmx[i]); }
        int c = cl[b];
        atomicMin(&g_cmin_u[c], flipf(MN));   // order-independent -> deterministic
        atomicMax(&g_cmax_u[c], flipf(MX));
    }
}

// -------- Kernel 3: elementwise fake-quant (268MB read + 268MB write) ------
__global__ void k3_quant(const float* __restrict__ x, float* __restrict__ out,
                         const float* __restrict__ act_range,
                         const int* __restrict__ cl) {
    int bc = blockIdx.x;
    int b  = bc >> 8;
    int t  = threadIdx.x;
    const float4* xv = (const float4*)(x + (size_t)bc * HW);
    float4* ov = (float4*)(out + (size_t)bc * HW);
    // issue the big loads first so the param computation hides behind them
    float4 v0 = xv[t], v1 = xv[t + 256], v2 = xv[t + 512], v3 = xv[t + 768];
    float sc = g_scale[bc];
    __shared__ float sp[3];
    if (t == 0) {
        int c = cl[b];
        float cmin = unflipf(g_cmin_u[c]);
        float cmax = unflipf(g_cmax_u[c]);
        float nmin = act_range[2*c + 0] * 0.995f + cmin * 0.005f;
        float nmax = act_range[2*c + 1] * 0.995f + cmax * 0.005f;
        float s = (nmax - nmin) / 255.0f;
        float z = -rintf(nmin / s);
        sp[0] = s; sp[1] = z; sp[2] = 1.0f / s;
    }
    __syncthreads();
    float ssv = sp[0], zzv = sp[1], inv = sp[2];
    float4 r0, r1, r2, r3;
#define FQ(V, R, F) {                               \
        float o  = sc * V.F;                        \
        float y0 = o * inv;                         \
        float rr = fmaf(-ssv, y0, o);               \
        float y  = fmaf(rr, inv, y0);   /* ~correctly rounded o/ssv */ \
        float q  = rintf(y + zzv);                  \
        q = fminf(fmaxf(q, 0.0f), 255.0f);          \
        R.F = (q - zzv) * ssv; }
#define FQ4(V, R) FQ(V, R, x) FQ(V, R, y) FQ(V, R, z) FQ(V, R, w)
    FQ4(v0, r0) FQ4(v1, r1) FQ4(v2, r2) FQ4(v3, r3)
#undef FQ4
#undef FQ
    ov[t]       = r0;
    ov[t + 256] = r1;
    ov[t + 512] = r2;
    ov[t + 768] = r3;
}

extern "C" void kernel_launch(void* const* d_in, const int* in_sizes, int n_in,
                              void* d_out, int out_size) {
    const float* x         = (const float*)d_in[0];
    const float* w1        = (const float*)d_in[1];
    const float* b1        = (const float*)d_in[2];
    const float* w2        = (const float*)d_in[3];
    const float* b2        = (const float*)d_in[4];
    const float* act_range = (const float*)d_in[5];
    const int*   scl       = (const int*)d_in[6];
    float* out = (float*)d_out;

    k1_stats<<<BB*CC/8, 256>>>(x);                 // 2048 blocks, warp-per-plane
    k2_scale<<<BB, 256>>>(w1, b1, w2, b2, scl);
    k3_quant<<<BB*CC, 256>>>(x, out, act_range, scl);
    (void)in_sizes; (void)n_in; (void)out_size;
}

// round 5
// speedup vs baseline: 1.1408x; 1.1275x over previous
#include <cuda_runtime.h>
#include <math_constants.h>

#define BB 64
#define CC 256
#define CS 64
#define HW 4096
#define NCL 8

// Scratch (allocation-free rule: __device__ globals)
__device__ float    g_pooled[BB*CC];
__device__ float    g_xmin[BB*CC];
__device__ float    g_xmax[BB*CC];
__device__ float    g_scale[BB*CC];
__device__ unsigned g_cmin_u[NCL];   // order-preserving-encoded cluster min
__device__ unsigned g_cmax_u[NCL];   // order-preserving-encoded cluster max

// Order-preserving float <-> uint encoding (monotone under unsigned compare)
__device__ __forceinline__ unsigned flipf(float f) {
    unsigned u = __float_as_uint(f);
    return (u & 0x80000000u) ? ~u : (u | 0x80000000u);
}
__device__ __forceinline__ float unflipf(unsigned u) {
    u = (u & 0x80000000u) ? (u & 0x7FFFFFFFu) : ~u;
    return __uint_as_float(u);
}

// -------- Kernel 1: per-(b,c) sum/min/max, warp-per-plane (268MB read) -----
__global__ void k1_stats(const float* __restrict__ x) {
    // reset cluster accumulators for this launch (k2 runs after -> ordered)
    if (blockIdx.x == 0 && threadIdx.x < NCL) {
        g_cmin_u[threadIdx.x] = 0xFFFFFFFFu;   // unsigned-min identity
        g_cmax_u[threadIdx.x] = 0u;            // unsigned-max identity
    }
    int plane = (blockIdx.x * blockDim.x + threadIdx.x) >> 5;  // 0..16383
    int lane  = threadIdx.x & 31;
    const float4* xv = (const float4*)(x + (size_t)plane * HW);
    float s = 0.f, mn = CUDART_INF_F, mx = -CUDART_INF_F;
#pragma unroll 8
    for (int j = 0; j < 32; j++) {
        float4 v = xv[lane + j * 32];
        s += (v.x + v.y) + (v.z + v.w);
        mn = fminf(mn, fminf(fminf(v.x, v.y), fminf(v.z, v.w)));
        mx = fmaxf(mx, fmaxf(fmaxf(v.x, v.y), fmaxf(v.z, v.w)));
    }
#pragma unroll
    for (int o = 16; o > 0; o >>= 1) {
        s  += __shfl_xor_sync(0xFFFFFFFFu, s, o);
        mn  = fminf(mn, __shfl_xor_sync(0xFFFFFFFFu, mn, o));
        mx  = fmaxf(mx, __shfl_xor_sync(0xFFFFFFFFu, mx, o));
    }
    if (lane == 0) {
        g_pooled[plane] = s * (1.0f / HW);
        g_xmin[plane]   = mn;
        g_xmax[plane]   = mx;
    }
}

// -------- Kernel 2: SE MLP + hardsigmoid + per-sample min/max -> cluster ---
// Layer 1: warp w computes outputs s = w*8..w*8+7; lane l handles c = l+32j
// (coalesced w1 reads, 8-way MLP, shuffle reduce). Layer 2: float4 w2 reads.
__global__ void k2_scale(const float* __restrict__ w1, const float* __restrict__ b1,
                         const float* __restrict__ w2, const float* __restrict__ b2,
                         const int* __restrict__ cl) {
    int b = blockIdx.x;       // 0..63
    int t = threadIdx.x;      // 256
    int w = t >> 5, l = t & 31;
    __shared__ float sp[CC], sh[CS];
    sp[t] = g_pooled[b*CC + t];
    __syncthreads();
#pragma unroll
    for (int i = 0; i < 8; i++) {
        int s = w * 8 + i;
        const float* wr = w1 + s * CC;
        float acc = 0.0f;
#pragma unroll
        for (int j = 0; j < 8; j++)
            acc = fmaf(sp[l + 32*j], wr[l + 32*j], acc);   // coalesced 128B/iter
#pragma unroll
        for (int o = 16; o > 0; o >>= 1)
            acc += __shfl_xor_sync(0xFFFFFFFFu, acc, o);
        if (l == 0) sh[s] = fmaxf(acc + b1[s], 0.0f);      // relu
    }
    __syncthreads();
    float v = b2[t];
    const float4* w2r = (const float4*)(w2 + t * CS);      // row t contiguous
#pragma unroll
    for (int s4 = 0; s4 < 16; s4++) {
        float4 ww = w2r[s4];
        v = fmaf(sh[4*s4 + 0], ww.x, v);
        v = fmaf(sh[4*s4 + 1], ww.y, v);
        v = fmaf(sh[4*s4 + 2], ww.z, v);
        v = fmaf(sh[4*s4 + 3], ww.w, v);
    }
    float sc = fminf(fmaxf(v / 6.0f + 0.5f, 0.0f), 1.0f);  // hardsigmoid
    g_scale[b*CC + t] = sc;
    // scale >= 0  =>  plane extrema factor through per-(b,c) extrema
    float pm = sc * g_xmin[b*CC + t];
    float pM = sc * g_xmax[b*CC + t];
#pragma unroll
    for (int o = 16; o > 0; o >>= 1) {
        pm = fminf(pm, __shfl_xor_sync(0xFFFFFFFFu, pm, o));
        pM = fmaxf(pM, __shfl_xor_sync(0xFFFFFFFFu, pM, o));
    }
    __shared__ float rmn[8], rmx[8];
    if (l == 0) { rmn[w] = pm; rmx[w] = pM; }
    __syncthreads();
    if (t == 0) {
        float MN = rmn[0], MX = rmx[0];
#pragma unroll
        for (int i = 1; i < 8; i++) { MN = fminf(MN, rmn[i]); MX = fmaxf(MX, rmx[i]); }
        int c = cl[b];
        atomicMin(&g_cmin_u[c], flipf(MN));   // order-independent -> deterministic
        atomicMax(&g_cmax_u[c], flipf(MX));
    }
}

// -------- Kernel 3: elementwise fake-quant (268MB read + 268MB write) ------
__global__ void k3_quant(const float* __restrict__ x, float* __restrict__ out,
                         const float* __restrict__ act_range,
                         const int* __restrict__ cl) {
    int bc = blockIdx.x;
    int b  = bc >> 8;
    int t  = threadIdx.x;
    const float4* xv = (const float4*)(x + (size_t)bc * HW);
    float4* ov = (float4*)(out + (size_t)bc * HW);
    // issue the big loads first so the param computation hides behind them
    float4 v0 = xv[t], v1 = xv[t + 256], v2 = xv[t + 512], v3 = xv[t + 768];
    float sc = g_scale[bc];
    __shared__ float sp[3];
    if (t == 0) {
        int c = cl[b];
        float cmin = unflipf(g_cmin_u[c]);
        float cmax = unflipf(g_cmax_u[c]);
        float nmin = act_range[2*c + 0] * 0.995f + cmin * 0.005f;
        float nmax = act_range[2*c + 1] * 0.995f + cmax * 0.005f;
        float s = (nmax - nmin) / 255.0f;
        float z = -rintf(nmin / s);
        sp[0] = s; sp[1] = z; sp[2] = 1.0f / s;
    }
    __syncthreads();
    float ssv = sp[0], zzv = sp[1], inv = sp[2];
    float4 r0, r1, r2, r3;
#define FQ(V, R, F) {                               \
        float o  = sc * V.F;                        \
        float y0 = o * inv;                         \
        float rr = fmaf(-ssv, y0, o);               \
        float y  = fmaf(rr, inv, y0);   /* ~correctly rounded o/ssv */ \
        float q  = rintf(y + zzv);                  \
        q = fminf(fmaxf(q, 0.0f), 255.0f);          \
        R.F = (q - zzv) * ssv; }
#define FQ4(V, R) FQ(V, R, x) FQ(V, R, y) FQ(V, R, z) FQ(V, R, w)
    FQ4(v0, r0) FQ4(v1, r1) FQ4(v2, r2) FQ4(v3, r3)
#undef FQ4
#undef FQ
    ov[t]       = r0;
    ov[t + 256] = r1;
    ov[t + 512] = r2;
    ov[t + 768] = r3;
}

extern "C" void kernel_launch(void* const* d_in, const int* in_sizes, int n_in,
                              void* d_out, int out_size) {
    const float* x         = (const float*)d_in[0];
    const float* w1        = (const float*)d_in[1];
    const float* b1        = (const float*)d_in[2];
    const float* w2        = (const float*)d_in[3];
    const float* b2        = (const float*)d_in[4];
    const float* act_range = (const float*)d_in[5];
    const int*   scl       = (const int*)d_in[6];
    float* out = (float*)d_out;

    k1_stats<<<BB*CC/8, 256>>>(x);                 // 2048 blocks, warp-per-plane
    k2_scale<<<BB, 256>>>(w1, b1, w2, b2, scl);
    k3_quant<<<BB*CC, 256>>>(x, out, act_range, scl);
    (void)in_sizes; (void)n_in; (void)out_size;
}